// round 10
// baseline (speedup 1.0000x reference)
#include <cuda_runtime.h>
#include <cuda_fp16.h>
#include <cstdint>

#define F_DIM 128
#define MAX_NODES 100000
#define MAX_EDGES 3200000
#define SCAN_BLK 1024
#define MAX_SCAN_BLOCKS ((MAX_NODES + SCAN_BLK - 1) / SCAN_BLK + 2)
#define KT 32
#define SPAD (KT + 4)
#define EPW 128   // edges per warp in flat accum

// Scratch (__device__ globals per harness rules)
__device__ float2 g_yh2[(size_t)MAX_NODES * (F_DIM / 4)]; // fp16 y (half2 pairs)
__device__ int    g_count[MAX_NODES + 1];
__device__ int    g_start[MAX_NODES + 1];
__device__ int    g_cursor[MAX_NODES];
__device__ int    g_blocksums[MAX_SCAN_BLOCKS];
__device__ int2   g_edges[MAX_EDGES];          // packed (col, val-as-int)

__device__ __forceinline__ uint32_t f32_to_tf32(float f) {
    uint32_t u;
    asm("cvt.rna.tf32.f32 %0, %1;" : "=r"(u) : "f"(f));
    return u;
}

// ---------------------------------------------------------------------------
// Kernel 1: y = x @ W^T -> fp16 via mma.sync tf32 tensor cores. (proven)
// ---------------------------------------------------------------------------
__global__ __launch_bounds__(256, 2)
void gemm_tf32_kernel(const float* __restrict__ x, const float* __restrict__ W,
                      int n_nodes) {
    __shared__ uint32_t As[128][SPAD];
    __shared__ uint32_t Ws[128][SPAD];

    const int tid  = threadIdx.x;
    const int warp = tid >> 5;
    const int lane = tid & 31;
    const int g    = lane >> 2;
    const int t    = lane & 3;
    const int m0   = blockIdx.x * 128;

    float c[16][4];
#pragma unroll
    for (int nt = 0; nt < 16; nt++)
#pragma unroll
        for (int i = 0; i < 4; i++) c[nt][i] = 0.0f;

    for (int kt = 0; kt < F_DIM; kt += KT) {
#pragma unroll
        for (int i = 0; i < 4; i++) {
            const int idx = tid + i * 256;
            const int r   = idx >> 3;
            const int cq  = (idx & 7) * 4;

            float4 av = make_float4(0.f, 0.f, 0.f, 0.f);
            if (m0 + r < n_nodes)
                av = *(const float4*)(x + (size_t)(m0 + r) * F_DIM + kt + cq);
            As[r][cq + 0] = f32_to_tf32(av.x);
            As[r][cq + 1] = f32_to_tf32(av.y);
            As[r][cq + 2] = f32_to_tf32(av.z);
            As[r][cq + 3] = f32_to_tf32(av.w);

            const float4 wv = *(const float4*)(W + (size_t)r * F_DIM + kt + cq);
            Ws[r][cq + 0] = f32_to_tf32(wv.x);
            Ws[r][cq + 1] = f32_to_tf32(wv.y);
            Ws[r][cq + 2] = f32_to_tf32(wv.z);
            Ws[r][cq + 3] = f32_to_tf32(wv.w);
        }
        __syncthreads();

#pragma unroll
        for (int ks = 0; ks < KT; ks += 8) {
            const uint32_t a0 = As[warp * 16 + g    ][ks + t];
            const uint32_t a1 = As[warp * 16 + g + 8][ks + t];
            const uint32_t a2 = As[warp * 16 + g    ][ks + t + 4];
            const uint32_t a3 = As[warp * 16 + g + 8][ks + t + 4];
#pragma unroll
            for (int nt = 0; nt < 16; nt++) {
                const uint32_t b0 = Ws[nt * 8 + g][ks + t];
                const uint32_t b1 = Ws[nt * 8 + g][ks + t + 4];
                asm volatile(
                    "mma.sync.aligned.m16n8k8.row.col.f32.tf32.tf32.f32 "
                    "{%0,%1,%2,%3}, {%4,%5,%6,%7}, {%8,%9}, {%0,%1,%2,%3};"
                    : "+f"(c[nt][0]), "+f"(c[nt][1]), "+f"(c[nt][2]), "+f"(c[nt][3])
                    : "r"(a0), "r"(a1), "r"(a2), "r"(a3), "r"(b0), "r"(b1));
            }
        }
        __syncthreads();
    }

    __half* yh = (__half*)g_yh2;
    const int r0 = m0 + warp * 16 + g;
    const int r1 = r0 + 8;
#pragma unroll
    for (int nt = 0; nt < 16; nt++) {
        const int col = nt * 8 + 2 * t;
        if (r0 < n_nodes)
            *(__half2*)(yh + (size_t)r0 * F_DIM + col) =
                __floats2half2_rn(c[nt][0], c[nt][1]);
        if (r1 < n_nodes)
            *(__half2*)(yh + (size_t)r1 * F_DIM + col) =
                __floats2half2_rn(c[nt][2], c[nt][3]);
    }
}

// ---------------------------------------------------------------------------
__global__ void zero_count_kernel(int n_nodes) {
    const int i = blockIdx.x * blockDim.x + threadIdx.x;
    if (i <= n_nodes) g_count[i] = 0;
}

// hist: 4 edges per thread (int4), streaming loads.
__global__ __launch_bounds__(256)
void hist_kernel(const int* __restrict__ rows, int n_edges) {
    const int base = (blockIdx.x * blockDim.x + threadIdx.x) * 4;
    if (base + 3 < n_edges) {
        const int4 r4 = __ldcs((const int4*)(rows + base));
        atomicAdd(&g_count[r4.x], 1);
        atomicAdd(&g_count[r4.y], 1);
        atomicAdd(&g_count[r4.z], 1);
        atomicAdd(&g_count[r4.w], 1);
    } else {
        for (int e = base; e < n_edges; e++)
            atomicAdd(&g_count[__ldcs(rows + e)], 1);
    }
}

// ---------------------------------------------------------------------------
// 3-kernel exclusive scan (proven ~6-7 us total on full chip).
// ---------------------------------------------------------------------------
__global__ __launch_bounds__(SCAN_BLK)
void scan1_kernel(int n) {
    __shared__ int s[SCAN_BLK];
    const int i = blockIdx.x * SCAN_BLK + threadIdx.x;
    const int v = (i < n) ? g_count[i] : 0;
    s[threadIdx.x] = v;
    __syncthreads();
#pragma unroll
    for (int d = 1; d < SCAN_BLK; d <<= 1) {
        int tt = (threadIdx.x >= d) ? s[threadIdx.x - d] : 0;
        __syncthreads();
        s[threadIdx.x] += tt;
        __syncthreads();
    }
    if (i < n) g_start[i] = s[threadIdx.x] - v;
    if (threadIdx.x == SCAN_BLK - 1) g_blocksums[blockIdx.x] = s[SCAN_BLK - 1];
}

__global__ void scan2_kernel(int nblocks, int n) {
    if (threadIdx.x == 0 && blockIdx.x == 0) {
        int acc = 0;
        for (int i = 0; i < nblocks; i++) {
            int t = g_blocksums[i];
            g_blocksums[i] = acc;
            acc += t;
        }
        g_start[n] = acc;
    }
}

__global__ __launch_bounds__(256)
void scan3_kernel(int n) {
    const int i = blockIdx.x * blockDim.x + threadIdx.x;
    if (i < n) {
        const int v = g_start[i] + g_blocksums[i >> 10];
        g_start[i]  = v;
        g_cursor[i] = v;
    }
}

// reorder: 1 edge/thread (R6-proven form).
__global__ __launch_bounds__(256)
void reorder_kernel(const int* __restrict__ rows, const int* __restrict__ cols,
                    const float* __restrict__ vals, int n_edges) {
    const int e = blockIdx.x * blockDim.x + threadIdx.x;
    if (e < n_edges) {
        const int   r = __ldcs(rows + e);
        const int   c = __ldcs(cols + e);
        const float v = __ldcs(vals + e);
        const int pos = atomicAdd(&g_cursor[r], 1);
        __stcs(&g_edges[pos], make_int2(c, __float_as_int(v)));
    }
}

// ---------------------------------------------------------------------------
// init: out[n][f] = b[f]  (accum flushes on top with red.add)
// ---------------------------------------------------------------------------
__global__ __launch_bounds__(256)
void init_bias_kernel(float4* __restrict__ out4, const float4* __restrict__ b4,
                      int total4) {
    const int i = blockIdx.x * blockDim.x + threadIdx.x;
    if (i < total4) out4[i] = b4[i & 31];
}

// ---------------------------------------------------------------------------
// Flat accum: each warp owns EPW consecutive sorted edges (perfect balance).
// Lane l accumulates features [4l, 4l+4); on node-boundary crossing, flush
// partials with red.global.add.v4.f32 into the bias-initialized out.
// ---------------------------------------------------------------------------
__global__ __launch_bounds__(256)
void flat_accum_kernel(float* __restrict__ out, int n_edges, int n_nodes) {
    const int warp = (blockIdx.x * blockDim.x + threadIdx.x) >> 5;
    const int lane = threadIdx.x & 31;
    const int base = warp * EPW;
    if (base >= n_edges) return;

    // Binary search: node = max i with g_start[i] <= base (converged; L2 broadcast)
    int lo = 0, hi = n_nodes;
    while (lo < hi) {
        const int mid = (lo + hi + 1) >> 1;
        if (g_start[mid] <= base) lo = mid; else hi = mid - 1;
    }
    int node     = lo;
    int node_end = g_start[node + 1];

    float a0 = 0.f, a1 = 0.f, a2 = 0.f, a3 = 0.f;
    bool dirty = false;

#pragma unroll
    for (int bb = 0; bb < EPW; bb += 32) {
        const int bstart = base + bb;
        if (bstart >= n_edges) break;
        const int idx0 = bstart + lane;
        int2 ed = make_int2(0, 0);
        if (idx0 < n_edges) ed = __ldcs(&g_edges[idx0]);
        const int lim = min(32, n_edges - bstart);

#pragma unroll 8
        for (int j = 0; j < 32; j++) {
            if (j >= lim) break;
            const int idx = bstart + j;
            while (idx >= node_end) {
                if (dirty) {
                    float* dst = out + (size_t)node * F_DIM + lane * 4;
                    asm volatile("red.global.add.v4.f32 [%0], {%1,%2,%3,%4};"
                                 :: "l"(dst), "f"(a0), "f"(a1), "f"(a2), "f"(a3)
                                 : "memory");
                    a0 = a1 = a2 = a3 = 0.f;
                    dirty = false;
                }
                node++;
                node_end = g_start[node + 1];
            }
            const int   col = __shfl_sync(0xffffffffu, ed.x, j);
            const float val = __int_as_float(__shfl_sync(0xffffffffu, ed.y, j));
            const float2 yv = g_yh2[(size_t)col * 32 + lane];
            const float2 f0 = __half22float2(*(const __half2*)&yv.x);
            const float2 f1 = __half22float2(*(const __half2*)&yv.y);
            a0 = fmaf(f0.x, val, a0);
            a1 = fmaf(f0.y, val, a1);
            a2 = fmaf(f1.x, val, a2);
            a3 = fmaf(f1.y, val, a3);
            dirty = true;
        }
    }

    if (dirty) {
        float* dst = out + (size_t)node * F_DIM + lane * 4;
        asm volatile("red.global.add.v4.f32 [%0], {%1,%2,%3,%4};"
                     :: "l"(dst), "f"(a0), "f"(a1), "f"(a2), "f"(a3)
                     : "memory");
    }
}

// ---------------------------------------------------------------------------
extern "C" void kernel_launch(void* const* d_in, const int* in_sizes, int n_in,
                              void* d_out, int out_size) {
    const int*   rows = (const int*)d_in[0];
    const int*   cols = (const int*)d_in[1];
    const float* vals = (const float*)d_in[2];
    const float* x    = (const float*)d_in[3];
    const float* W    = (const float*)d_in[4];
    const float* b    = (const float*)d_in[5];
    float*       out  = (float*)d_out;

    const int n_edges = in_sizes[0];
    const int n_nodes = in_sizes[3] / F_DIM;
    const int nblocks_scan = (n_nodes + SCAN_BLK - 1) / SCAN_BLK;

    static cudaStream_t s2 = nullptr;
    static cudaEvent_t ev_fork = nullptr, ev_join = nullptr;
    if (s2 == nullptr) {
        cudaStreamCreateWithFlags(&s2, cudaStreamNonBlocking);
        cudaEventCreateWithFlags(&ev_fork, cudaEventDisableTiming);
        cudaEventCreateWithFlags(&ev_join, cudaEventDisableTiming);
    }

    // Fork: GEMM + bias-init on the side stream (short branch, ~40 us).
    cudaEventRecord(ev_fork, 0);
    cudaStreamWaitEvent(s2, ev_fork, 0);

    gemm_tf32_kernel<<<(n_nodes + 127) / 128, 256, 0, s2>>>(x, W, n_nodes);
    {
        const int total4 = n_nodes * (F_DIM / 4);
        init_bias_kernel<<<(total4 + 255) / 256, 256, 0, s2>>>(
            (float4*)out, (const float4*)b, total4);
    }

    // Main (critical): CSR build (~60 us).
    zero_count_kernel<<<(n_nodes + 256) / 256, 256>>>(n_nodes);
    {
        const int threads_needed = (n_edges + 3) / 4;
        hist_kernel<<<(threads_needed + 255) / 256, 256>>>(rows, n_edges);
    }
    scan1_kernel<<<nblocks_scan, SCAN_BLK>>>(n_nodes);
    scan2_kernel<<<1, 32>>>(nblocks_scan, n_nodes);
    scan3_kernel<<<(n_nodes + 255) / 256, 256>>>(n_nodes);
    reorder_kernel<<<(n_edges + 255) / 256, 256>>>(rows, cols, vals, n_edges);

    // Join
    cudaEventRecord(ev_join, s2);
    cudaStreamWaitEvent(0, ev_join, 0);

    // Flat, perfectly-balanced gather-accumulate.
    {
        const int n_warps  = (n_edges + EPW - 1) / EPW;
        const int n_blocks = (n_warps * 32 + 255) / 256;
        flat_accum_kernel<<<n_blocks, 256>>>(out, n_edges, n_nodes);
    }
}